// round 4
// baseline (speedup 1.0000x reference)
#include <cuda_runtime.h>
#include <math.h>

// Problem constants (fixed shapes from reference)
#define NROWS 8192          // N == M
#define DDIM  1024
static __device__ __constant__ float kTempInv = 14.2857142857142857f;  // 1/0.07

// ---- scratch (no runtime allocation allowed) ----
__device__ float  g_fa[(size_t)NROWS * DDIM];   // normalized A
__device__ float  g_fb[(size_t)NROWS * DDIM];   // normalized B
__device__ double g_pos[NROWS];
__device__ double g_neg[NROWS];

// ---------------------------------------------------------------------------
// zero accumulators (graph replays reuse them)
// ---------------------------------------------------------------------------
__global__ void zero_kernel() {
    int i = blockIdx.x * blockDim.x + threadIdx.x;
    if (i < NROWS) { g_pos[i] = 0.0; g_neg[i] = 0.0; }
}

// ---------------------------------------------------------------------------
// row L2-normalize: one block per row, 256 threads, 1 float4 per thread
// ---------------------------------------------------------------------------
__global__ void normalize_kernel(const float* __restrict__ A,
                                 const float* __restrict__ B) {
    int row = blockIdx.x;
    const float* src;
    float* dst;
    if (row < NROWS) {
        src = A + (size_t)row * DDIM;
        dst = g_fa + (size_t)row * DDIM;
    } else {
        src = B + (size_t)(row - NROWS) * DDIM;
        dst = g_fb + (size_t)(row - NROWS) * DDIM;
    }
    int t = threadIdx.x;  // 256 threads * 4 floats = 1024
    float4 v = reinterpret_cast<const float4*>(src)[t];
    float s = v.x * v.x + v.y * v.y + v.z * v.z + v.w * v.w;

    // warp reduce
    #pragma unroll
    for (int off = 16; off > 0; off >>= 1)
        s += __shfl_xor_sync(0xffffffffu, s, off);

    __shared__ float ws[8];
    if ((t & 31) == 0) ws[t >> 5] = s;
    __syncthreads();
    if (t < 32) {
        float x = (t < 8) ? ws[t] : 0.0f;
        #pragma unroll
        for (int off = 4; off > 0; off >>= 1)
            x += __shfl_xor_sync(0xffffffffu, x, off);
        if (t == 0) ws[0] = x;
    }
    __syncthreads();
    float norm = sqrtf(ws[0]);
    float scale = 1.0f / fmaxf(norm, 1e-12f);
    v.x *= scale; v.y *= scale; v.z *= scale; v.w *= scale;
    reinterpret_cast<float4*>(dst)[t] = v;
}

// ---------------------------------------------------------------------------
// fused GEMM + exp + masked row-sum epilogue
// BM=BN=128, BK=16, 256 threads, 8x8 microtile per thread
// ---------------------------------------------------------------------------
#define BM 128
#define BN 128
#define BK 16

__global__ __launch_bounds__(256, 2)
void gemm_epilogue_kernel(const int* __restrict__ la,
                          const int* __restrict__ lb) {
    __shared__ float As[BK][BM];
    __shared__ float Bs[BK][BN];
    __shared__ int sla[BM];
    __shared__ int slb[BN];

    const int bm0 = blockIdx.y * BM;
    const int bn0 = blockIdx.x * BN;
    const int tid = threadIdx.x;
    const int ty  = tid >> 4;   // 0..15
    const int tx  = tid & 15;   // 0..15

    if (tid < BM) {
        sla[tid] = la[bm0 + tid];
        slb[tid] = lb[bn0 + tid];
    }

    float acc[8][8];
    #pragma unroll
    for (int i = 0; i < 8; i++)
        #pragma unroll
        for (int j = 0; j < 8; j++)
            acc[i][j] = 0.0f;

    // tile loads: 128 rows x 16 cols = 512 float4, 256 threads -> 2 each
    for (int k0 = 0; k0 < DDIM; k0 += BK) {
        __syncthreads();
        #pragma unroll
        for (int qq = 0; qq < 2; qq++) {
            int q  = tid + qq * 256;
            int r  = q >> 2;            // row within tile
            int c4 = (q & 3) * 4;       // k offset within BK
            float4 va = *reinterpret_cast<const float4*>(
                &g_fa[(size_t)(bm0 + r) * DDIM + k0 + c4]);
            As[c4 + 0][r] = va.x; As[c4 + 1][r] = va.y;
            As[c4 + 2][r] = va.z; As[c4 + 3][r] = va.w;
            float4 vb = *reinterpret_cast<const float4*>(
                &g_fb[(size_t)(bn0 + r) * DDIM + k0 + c4]);
            Bs[c4 + 0][r] = vb.x; Bs[c4 + 1][r] = vb.y;
            Bs[c4 + 2][r] = vb.z; Bs[c4 + 3][r] = vb.w;
        }
        __syncthreads();

        #pragma unroll
        for (int k = 0; k < BK; k++) {
            float a[8], b[8];
            float4 a0 = *reinterpret_cast<const float4*>(&As[k][ty * 8 + 0]);
            float4 a1 = *reinterpret_cast<const float4*>(&As[k][ty * 8 + 4]);
            float4 b0 = *reinterpret_cast<const float4*>(&Bs[k][tx * 8 + 0]);
            float4 b1 = *reinterpret_cast<const float4*>(&Bs[k][tx * 8 + 4]);
            a[0]=a0.x; a[1]=a0.y; a[2]=a0.z; a[3]=a0.w;
            a[4]=a1.x; a[5]=a1.y; a[6]=a1.z; a[7]=a1.w;
            b[0]=b0.x; b[1]=b0.y; b[2]=b0.z; b[3]=b0.w;
            b[4]=b1.x; b[5]=b1.y; b[6]=b1.z; b[7]=b1.w;
            #pragma unroll
            for (int i = 0; i < 8; i++)
                #pragma unroll
                for (int j = 0; j < 8; j++)
                    acc[i][j] = fmaf(a[i], b[j], acc[i][j]);
        }
    }

    // epilogue: sim -> clip -> exp -> masked row sums
    int myla[8];
    int mylb[8];
    #pragma unroll
    for (int i = 0; i < 8; i++) myla[i] = sla[ty * 8 + i];
    #pragma unroll
    for (int j = 0; j < 8; j++) mylb[j] = slb[tx * 8 + j];

    #pragma unroll
    for (int i = 0; i < 8; i++) {
        float psum = 0.0f, nsum = 0.0f;
        #pragma unroll
        for (int j = 0; j < 8; j++) {
            float sim = acc[i][j] * kTempInv;
            sim = fminf(fmaxf(sim, -50.0f), 50.0f);
            float e = __expf(sim);
            nsum += e;
            if (myla[i] == mylb[j]) psum += e;
        }
        // reduce across the 16 tx lanes (contiguous 16-lane segment)
        #pragma unroll
        for (int off = 8; off > 0; off >>= 1) {
            psum += __shfl_xor_sync(0xffffffffu, psum, off, 16);
            nsum += __shfl_xor_sync(0xffffffffu, nsum, off, 16);
        }
        if (tx == 0) {
            int row = bm0 + ty * 8 + i;
            atomicAdd(&g_pos[row], (double)psum);
            atomicAdd(&g_neg[row], (double)nsum);
        }
    }
}

// ---------------------------------------------------------------------------
// finalize: loss = -mean(log(max(pos,1e-8)/neg))
// ---------------------------------------------------------------------------
__global__ void finalize_kernel(float* __restrict__ out) {
    int t = threadIdx.x;  // 256
    double local = 0.0;
    for (int i = t; i < NROWS; i += 256) {
        double p = g_pos[i];
        if (p < 1e-8) p = 1e-8;
        double n = g_neg[i];
        local += log(p) - log(n);
    }
    // block reduce in double
    #pragma unroll
    for (int off = 16; off > 0; off >>= 1)
        local += __shfl_xor_sync(0xffffffffu, local, off);
    __shared__ double ws[8];
    if ((t & 31) == 0) ws[t >> 5] = local;
    __syncthreads();
    if (t == 0) {
        double tot = 0.0;
        #pragma unroll
        for (int w = 0; w < 8; w++) tot += ws[w];
        out[0] = (float)(-tot / (double)NROWS);
    }
}

// ---------------------------------------------------------------------------
extern "C" void kernel_launch(void* const* d_in, const int* in_sizes, int n_in,
                              void* d_out, int out_size) {
    const float* fa = (const float*)d_in[0];
    const float* fb = (const float*)d_in[1];
    const int*   la = (const int*)d_in[2];
    const int*   lb = (const int*)d_in[3];
    float* out = (float*)d_out;

    zero_kernel<<<(NROWS + 255) / 256, 256>>>();
    normalize_kernel<<<2 * NROWS, 256>>>(fa, fb);
    dim3 grid(NROWS / BN, NROWS / BM);
    gemm_epilogue_kernel<<<grid, 256>>>(la, lb);
    finalize_kernel<<<1, 256>>>(out);
}

// round 6
// speedup vs baseline: 7.3300x; 7.3300x over previous
#include <cuda_runtime.h>
#include <cuda_fp16.h>
#include <cstdint>
#include <math.h>

// ---------------- problem constants ----------------
#define NROWS 8192
#define DDIM  1024
#define BM 128
#define BN 256
#define BK 64                 // k elems per chunk = 128 bytes/row
#define NCHUNK (DDIM / BK)    // 16
#define NSTAGE 4
#define THREADS 256

static __device__ __constant__ float kTempInv = 14.2857142857142857f;  // 1/0.07

// ---------------- scratch (no runtime allocation) ----------------
__device__ __half g_fa[(size_t)NROWS * DDIM];   // normalized A, fp16
__device__ __half g_fb[(size_t)NROWS * DDIM];   // normalized B, fp16
__device__ double g_pos[NROWS];
__device__ double g_neg[NROWS];

// ---------------- SMEM layout ----------------
#define A_BYTES (BM * 128)            // 16384
#define B_BYTES (BN * 128)            // 32768
#define STAGE_B (A_BYTES + B_BYTES)   // 49152
#define AUX_BASE (NSTAGE * STAGE_B)   // 196608
#define AUX_SLB  (AUX_BASE)           // 256*4
#define AUX_SLA  (AUX_BASE + 1024)    // 128*4
#define AUX_SPOS (AUX_BASE + 1536)    // 128*4
#define AUX_SNEG (AUX_BASE + 2048)    // 128*4
#define SMEM_TOTAL (AUX_BASE + 2560)  // 199168

#define SWZ(o) ((o) ^ (((o) >> 3) & 0x70))

__device__ __forceinline__ uint32_t smem_u32(const void* p) {
    uint32_t a;
    asm("{ .reg .u64 t; cvta.to.shared.u64 t, %1; cvt.u32.u64 %0, t; }"
        : "=r"(a) : "l"(p));
    return a;
}

#define LDSM_X4(r0, r1, r2, r3, addr) \
    asm volatile("ldmatrix.sync.aligned.m8n8.x4.shared.b16 {%0,%1,%2,%3}, [%4];" \
                 : "=r"(r0), "=r"(r1), "=r"(r2), "=r"(r3) : "r"(addr))

#define MMA16816(c, a, b0, b1) \
    asm volatile("mma.sync.aligned.m16n8k16.row.col.f32.f16.f16.f32 " \
                 "{%0,%1,%2,%3}, {%4,%5,%6,%7}, {%8,%9}, {%0,%1,%2,%3};" \
                 : "+f"((c)[0]), "+f"((c)[1]), "+f"((c)[2]), "+f"((c)[3]) \
                 : "r"((a)[0]), "r"((a)[1]), "r"((a)[2]), "r"((a)[3]), \
                   "r"(b0), "r"(b1))

#define CP_ASYNC16(dst, src) \
    asm volatile("cp.async.cg.shared.global [%0], [%1], 16;" :: "r"(dst), "l"(src))
#define CP_COMMIT() asm volatile("cp.async.commit_group;" ::: "memory")
#define CP_WAIT2()  asm volatile("cp.async.wait_group 2;" ::: "memory")

// ---------------------------------------------------------------------------
__global__ void zero_kernel() {
    int i = blockIdx.x * blockDim.x + threadIdx.x;
    if (i < NROWS) { g_pos[i] = 0.0; g_neg[i] = 0.0; }
}

// ---------------------------------------------------------------------------
// L2 normalize + fp16 convert. 2*NROWS blocks, 256 threads, 4 floats/thread.
// ---------------------------------------------------------------------------
__global__ void normalize_kernel(const float* __restrict__ A,
                                 const float* __restrict__ B) {
    int row = blockIdx.x;
    const float* src;
    __half* dst;
    if (row < NROWS) {
        src = A + (size_t)row * DDIM;
        dst = g_fa + (size_t)row * DDIM;
    } else {
        int r = row - NROWS;
        src = B + (size_t)r * DDIM;
        dst = g_fb + (size_t)r * DDIM;
    }
    int t = threadIdx.x;
    float4 v = reinterpret_cast<const float4*>(src)[t];
    float s = v.x * v.x + v.y * v.y + v.z * v.z + v.w * v.w;
    #pragma unroll
    for (int off = 16; off > 0; off >>= 1)
        s += __shfl_xor_sync(0xffffffffu, s, off);
    __shared__ float ws[8];
    if ((t & 31) == 0) ws[t >> 5] = s;
    __syncthreads();
    if (t < 32) {
        float x = (t < 8) ? ws[t] : 0.0f;
        #pragma unroll
        for (int off = 4; off > 0; off >>= 1)
            x += __shfl_xor_sync(0xffffffffu, x, off);
        if (t == 0) ws[0] = x;
    }
    __syncthreads();
    float scale = 1.0f / fmaxf(sqrtf(ws[0]), 1e-12f);

    __half2 h0 = __floats2half2_rn(v.x * scale, v.y * scale);
    __half2 h1 = __floats2half2_rn(v.z * scale, v.w * scale);
    __half2* p = reinterpret_cast<__half2*>(dst + t * 4);
    p[0] = h0;
    p[1] = h1;
}

// ---------------------------------------------------------------------------
// fp16 mma.sync GEMM (128x256 CTA tile) + fused exp/mask epilogue
// ---------------------------------------------------------------------------
extern __shared__ __align__(1024) char smem[];

__device__ __forceinline__ void load_stage(uint32_t sbase, int s, int c,
                                           int bm0, int bn0, int tid) {
    uint32_t aB = sbase + s * STAGE_B;
    uint32_t bB = aB + A_BYTES;
    const int k0 = c * BK;
    #pragma unroll
    for (int it = 0; it < 4; it++) {          // A: 128 rows x 8 chunks of 16B
        int idx = tid + it * THREADS;
        int r = idx >> 3, u = idx & 7;
        const void* src = g_fa + (size_t)(bm0 + r) * DDIM + k0 + u * 8;
        CP_ASYNC16(aB + SWZ(r * 128 + u * 16), src);
    }
    #pragma unroll
    for (int it = 0; it < 8; it++) {          // B: 256 rows x 8 chunks of 16B
        int idx = tid + it * THREADS;
        int r = idx >> 3, u = idx & 7;
        const void* src = g_fb + (size_t)(bn0 + r) * DDIM + k0 + u * 8;
        CP_ASYNC16(bB + SWZ(r * 128 + u * 16), src);
    }
    CP_COMMIT();
}

__global__ __launch_bounds__(THREADS, 1)
void gemm_mma_kernel(const int* __restrict__ la, const int* __restrict__ lb) {
    const int tid  = threadIdx.x;
    const int lane = tid & 31;
    const int wid  = tid >> 5;
    const int wm   = wid & 1;        // 2 warps along M
    const int wn   = wid >> 1;       // 4 warps along N
    const int bm0  = blockIdx.y * BM;
    const int bn0  = blockIdx.x * BN;

    int* sla = (int*)(smem + AUX_SLA);
    int* slb = (int*)(smem + AUX_SLB);
    float* spos = (float*)(smem + AUX_SPOS);
    float* sneg = (float*)(smem + AUX_SNEG);

    if (tid < BM) {
        sla[tid] = la[bm0 + tid];
        spos[tid] = 0.0f;
        sneg[tid] = 0.0f;
    }
    slb[tid] = lb[bn0 + tid];

    uint32_t sbase = smem_u32(smem);

    float acc[4][8][4];
    #pragma unroll
    for (int i = 0; i < 4; i++)
        #pragma unroll
        for (int j = 0; j < 8; j++)
            #pragma unroll
            for (int v = 0; v < 4; v++)
                acc[i][j][v] = 0.0f;

    // prologue: 3 stages in flight
    #pragma unroll
    for (int s = 0; s < 3; s++) load_stage(sbase, s, s, bm0, bn0, tid);

    const int rl = lane & 15;
    const int ch = lane >> 4;

    for (int c = 0; c < NCHUNK; c++) {
        CP_WAIT2();
        __syncthreads();

        uint32_t aB = sbase + (c & 3) * STAGE_B;
        uint32_t bB = aB + A_BYTES;

        #pragma unroll
        for (int ks = 0; ks < 4; ks++) {
            const int cb = ks * 32 + ch * 16;
            uint32_t a[4][4];
            #pragma unroll
            for (int i = 0; i < 4; i++) {
                int row = wm * 64 + i * 16 + rl;
                LDSM_X4(a[i][0], a[i][1], a[i][2], a[i][3],
                        aB + SWZ(row * 128 + cb));
            }
            #pragma unroll
            for (int jj = 0; jj < 4; jj++) {
                int row = wn * 64 + jj * 16 + rl;
                uint32_t b0, b1, b2, b3;
                LDSM_X4(b0, b1, b2, b3, bB + SWZ(row * 128 + cb));
                #pragma unroll
                for (int i = 0; i < 4; i++) {
                    MMA16816(acc[i][jj * 2 + 0], a[i], b0, b2);
                    MMA16816(acc[i][jj * 2 + 1], a[i], b1, b3);
                }
            }
        }
        __syncthreads();
        if (c + 3 < NCHUNK) load_stage(sbase, (c + 3) & 3, c + 3, bm0, bn0, tid);
    }

    // ----- epilogue: exp + label mask + row sums -----
    const int g  = lane >> 2;
    const int t4 = lane & 3;

    int rowlab[8];
    #pragma unroll
    for (int i = 0; i < 4; i++) {
        rowlab[2 * i + 0] = sla[wm * 64 + i * 16 + g];
        rowlab[2 * i + 1] = sla[wm * 64 + i * 16 + g + 8];
    }
    int collab[16];
    #pragma unroll
    for (int j = 0; j < 8; j++) {
        collab[2 * j + 0] = slb[wn * 64 + j * 8 + t4 * 2 + 0];
        collab[2 * j + 1] = slb[wn * 64 + j * 8 + t4 * 2 + 1];
    }

    float prow[8], nrow[8];
    #pragma unroll
    for (int k = 0; k < 8; k++) { prow[k] = 0.0f; nrow[k] = 0.0f; }

    #pragma unroll
    for (int i = 0; i < 4; i++)
        #pragma unroll
        for (int j = 0; j < 8; j++)
            #pragma unroll
            for (int v = 0; v < 4; v++) {
                float sim = acc[i][j][v] * kTempInv;
                sim = fminf(fmaxf(sim, -50.0f), 50.0f);
                float e = __expf(sim);
                int h = v >> 1;
                nrow[2 * i + h] += e;
                if (collab[2 * j + (v & 1)] == rowlab[2 * i + h])
                    prow[2 * i + h] += e;
            }

    // reduce across the 4 lanes of each quad (same row, different cols)
    #pragma unroll
    for (int off = 1; off <= 2; off <<= 1)
        #pragma unroll
        for (int k = 0; k < 8; k++) {
            prow[k] += __shfl_xor_sync(0xffffffffu, prow[k], off);
            nrow[k] += __shfl_xor_sync(0xffffffffu, nrow[k], off);
        }

    if (t4 == 0) {
        #pragma unroll
        for (int k = 0; k < 8; k++) {
            int row = wm * 64 + (k >> 1) * 16 + g + (k & 1) * 8;
            atomicAdd(&spos[row], prow[k]);
            atomicAdd(&sneg[row], nrow[k]);
        }
    }
    __syncthreads();
    if (tid < BM) {
        atomicAdd(&g_pos[bm0 + tid], (double)spos[tid]);
        atomicAdd(&g_neg[bm0 + tid], (double)sneg[tid]);
    }
}

// ---------------------------------------------------------------------------
// finalize: loss = -mean(log(max(pos,1e-8)/neg)), 1024 threads
// ---------------------------------------------------------------------------
__global__ void finalize_kernel(float* __restrict__ out) {
    int t = threadIdx.x;
    double local = 0.0;
    for (int i = t; i < NROWS; i += 1024) {
        double p = g_pos[i];
        if (p < 1e-8) p = 1e-8;
        local += (double)logf((float)(p / g_neg[i]));
    }
    #pragma unroll
    for (int off = 16; off > 0; off >>= 1)
        local += __shfl_xor_sync(0xffffffffu, local, off);
    __shared__ double ws[32];
    if ((t & 31) == 0) ws[t >> 5] = local;
    __syncthreads();
    if (t < 32) {
        double x = ws[t];
        #pragma unroll
        for (int off = 16; off > 0; off >>= 1)
            x += __shfl_xor_sync(0xffffffffu, x, off);
        if (t == 0) out[0] = (float)(-x / (double)NROWS);
    }
}

// ---------------------------------------------------------------------------
extern "C" void kernel_launch(void* const* d_in, const int* in_sizes, int n_in,
                              void* d_out, int out_size) {
    const float* fa = (const float*)d_in[0];
    const float* fb = (const float*)d_in[1];
    const int*   la = (const int*)d_in[2];
    const int*   lb = (const int*)d_in[3];
    float* out = (float*)d_out;

    cudaFuncSetAttribute(gemm_mma_kernel,
                         cudaFuncAttributeMaxDynamicSharedMemorySize, SMEM_TOTAL);

    zero_kernel<<<(NROWS + 255) / 256, 256>>>();
    normalize_kernel<<<2 * NROWS, 256>>>(fa, fb);
    dim3 grid(NROWS / BN, NROWS / BM);
    gemm_mma_kernel<<<grid, THREADS, SMEM_TOTAL>>>(la, lb);
    finalize_kernel<<<1, 1024>>>(out);
}

// round 7
// speedup vs baseline: 7.6154x; 1.0389x over previous
#include <cuda_runtime.h>
#include <cuda_fp16.h>
#include <cstdint>
#include <math.h>

// ---------------- problem constants ----------------
#define NROWS 8192
#define DDIM  1024
#define BM 128
#define BN 256
#define BK 64                 // k elems per chunk = 128 bytes/row
#define NCHUNK (DDIM / BK)    // 16
#define NSTAGE 4
#define THREADS 256

static __device__ __constant__ float kTempInv = 14.2857142857142857f;  // 1/0.07

// ---------------- scratch (no runtime allocation) ----------------
__device__ __half g_fa[(size_t)NROWS * DDIM];   // normalized A, fp16
__device__ __half g_fb[(size_t)NROWS * DDIM];   // normalized B, fp16
__device__ double g_pos[NROWS];
__device__ double g_neg[NROWS];
__device__ double g_loss;

// ---------------- SMEM layout ----------------
#define A_BYTES (BM * 128)            // 16384
#define B_BYTES (BN * 128)            // 32768
#define STAGE_B (A_BYTES + B_BYTES)   // 49152
#define AUX_BASE (NSTAGE * STAGE_B)   // 196608
#define AUX_SLB  (AUX_BASE)           // 256*4
#define AUX_SLA  (AUX_BASE + 1024)    // 128*4
#define AUX_SPOS (AUX_BASE + 1536)    // 128*4
#define AUX_SNEG (AUX_BASE + 2048)    // 128*4
#define SMEM_TOTAL (AUX_BASE + 2560)  // 199168

#define SWZ(o) ((o) ^ (((o) >> 3) & 0x70))

__device__ __forceinline__ uint32_t smem_u32(const void* p) {
    uint32_t a;
    asm("{ .reg .u64 t; cvta.to.shared.u64 t, %1; cvt.u32.u64 %0, t; }"
        : "=r"(a) : "l"(p));
    return a;
}

#define LDSM_X4(r0, r1, r2, r3, addr) \
    asm volatile("ldmatrix.sync.aligned.m8n8.x4.shared.b16 {%0,%1,%2,%3}, [%4];" \
                 : "=r"(r0), "=r"(r1), "=r"(r2), "=r"(r3) : "r"(addr))

#define MMA16816(c, a, b0, b1) \
    asm volatile("mma.sync.aligned.m16n8k16.row.col.f32.f16.f16.f32 " \
                 "{%0,%1,%2,%3}, {%4,%5,%6,%7}, {%8,%9}, {%0,%1,%2,%3};" \
                 : "+f"((c)[0]), "+f"((c)[1]), "+f"((c)[2]), "+f"((c)[3]) \
                 : "r"((a)[0]), "r"((a)[1]), "r"((a)[2]), "r"((a)[3]), \
                   "r"(b0), "r"(b1))

#define CP_ASYNC16(dst, src) \
    asm volatile("cp.async.cg.shared.global [%0], [%1], 16;" :: "r"(dst), "l"(src))
#define CP_COMMIT() asm volatile("cp.async.commit_group;" ::: "memory")

// ---------------------------------------------------------------------------
__global__ void zero_kernel() {
    int i = blockIdx.x * blockDim.x + threadIdx.x;
    if (i < NROWS) { g_pos[i] = 0.0; g_neg[i] = 0.0; }
    if (i == 0) g_loss = 0.0;
}

// ---------------------------------------------------------------------------
// L2 normalize + fp16 convert. 2*NROWS blocks, 256 threads, 4 floats/thread.
// ---------------------------------------------------------------------------
__global__ void normalize_kernel(const float* __restrict__ A,
                                 const float* __restrict__ B) {
    int row = blockIdx.x;
    const float* src;
    __half* dst;
    if (row < NROWS) {
        src = A + (size_t)row * DDIM;
        dst = g_fa + (size_t)row * DDIM;
    } else {
        int r = row - NROWS;
        src = B + (size_t)r * DDIM;
        dst = g_fb + (size_t)r * DDIM;
    }
    int t = threadIdx.x;
    float4 v = reinterpret_cast<const float4*>(src)[t];
    float s = v.x * v.x + v.y * v.y + v.z * v.z + v.w * v.w;
    #pragma unroll
    for (int off = 16; off > 0; off >>= 1)
        s += __shfl_xor_sync(0xffffffffu, s, off);
    __shared__ float ws[8];
    if ((t & 31) == 0) ws[t >> 5] = s;
    __syncthreads();
    if (t < 32) {
        float x = (t < 8) ? ws[t] : 0.0f;
        #pragma unroll
        for (int off = 4; off > 0; off >>= 1)
            x += __shfl_xor_sync(0xffffffffu, x, off);
        if (t == 0) ws[0] = x;
    }
    __syncthreads();
    float scale = 1.0f / fmaxf(sqrtf(ws[0]), 1e-12f);

    __half2 h0 = __floats2half2_rn(v.x * scale, v.y * scale);
    __half2 h1 = __floats2half2_rn(v.z * scale, v.w * scale);
    __half2* p = reinterpret_cast<__half2*>(dst + t * 4);
    p[0] = h0;
    p[1] = h1;
}

// ---------------------------------------------------------------------------
// fp16 mma.sync GEMM (128x256 CTA tile) + fused exp/mask epilogue
// ---------------------------------------------------------------------------
extern __shared__ __align__(1024) char smem[];

__device__ __forceinline__ void load_stage(uint32_t sbase, int s, int c,
                                           int bm0, int bn0, int tid) {
    uint32_t aB = sbase + s * STAGE_B;
    uint32_t bB = aB + A_BYTES;
    const int k0 = c * BK;
    #pragma unroll
    for (int it = 0; it < 4; it++) {          // A: 128 rows x 8 chunks of 16B
        int idx = tid + it * THREADS;
        int r = idx >> 3, u = idx & 7;
        const void* src = g_fa + (size_t)(bm0 + r) * DDIM + k0 + u * 8;
        CP_ASYNC16(aB + SWZ(r * 128 + u * 16), src);
    }
    #pragma unroll
    for (int it = 0; it < 8; it++) {          // B: 256 rows x 8 chunks of 16B
        int idx = tid + it * THREADS;
        int r = idx >> 3, u = idx & 7;
        const void* src = g_fb + (size_t)(bn0 + r) * DDIM + k0 + u * 8;
        CP_ASYNC16(bB + SWZ(r * 128 + u * 16), src);
    }
    CP_COMMIT();
}

__device__ __forceinline__ void compute_chunk(uint32_t aB, uint32_t bB,
                                              float (&acc)[4][8][4],
                                              int wm, int wn, int rl, int ch) {
    #pragma unroll
    for (int ks = 0; ks < 4; ks++) {
        const int cb = ks * 32 + ch * 16;
        uint32_t a[4][4];
        #pragma unroll
        for (int i = 0; i < 4; i++) {
            int row = wm * 64 + i * 16 + rl;
            LDSM_X4(a[i][0], a[i][1], a[i][2], a[i][3],
                    aB + SWZ(row * 128 + cb));
        }
        #pragma unroll
        for (int jj = 0; jj < 4; jj++) {
            int row = wn * 64 + jj * 16 + rl;
            uint32_t b0, b1, b2, b3;
            LDSM_X4(b0, b1, b2, b3, bB + SWZ(row * 128 + cb));
            #pragma unroll
            for (int i = 0; i < 4; i++) {
                MMA16816(acc[i][jj * 2 + 0], a[i], b0, b2);
                MMA16816(acc[i][jj * 2 + 1], a[i], b1, b3);
            }
        }
    }
}

__global__ __launch_bounds__(THREADS, 1)
void gemm_mma_kernel(const int* __restrict__ la, const int* __restrict__ lb) {
    const int tid  = threadIdx.x;
    const int lane = tid & 31;
    const int wid  = tid >> 5;
    const int wm   = wid & 1;        // 2 warps along M
    const int wn   = wid >> 1;       // 4 warps along N
    const int bm0  = blockIdx.y * BM;
    const int bn0  = blockIdx.x * BN;

    int* sla = (int*)(smem + AUX_SLA);
    int* slb = (int*)(smem + AUX_SLB);
    float* spos = (float*)(smem + AUX_SPOS);
    float* sneg = (float*)(smem + AUX_SNEG);

    if (tid < BM) {
        sla[tid] = la[bm0 + tid];
        spos[tid] = 0.0f;
        sneg[tid] = 0.0f;
    }
    slb[tid] = lb[bn0 + tid];

    uint32_t sbase = smem_u32(smem);

    float acc[4][8][4];
    #pragma unroll
    for (int i = 0; i < 4; i++)
        #pragma unroll
        for (int j = 0; j < 8; j++)
            #pragma unroll
            for (int v = 0; v < 4; v++)
                acc[i][j][v] = 0.0f;

    // prologue: 3 stages in flight
    #pragma unroll
    for (int s = 0; s < 3; s++) load_stage(sbase, s, s, bm0, bn0, tid);

    const int rl = lane & 15;
    const int ch = lane >> 4;

    // steady state: exactly one __syncthreads per chunk.
    // At iter c: wait_group 2 retires chunk c's group (3 pending: c, c+1, c+2);
    // after the barrier, issue chunk c+3 into buffer (c+3)&3 == (c-1)&3, whose
    // consumers all passed this same barrier. Then compute chunk c.
    #pragma unroll 1
    for (int c = 0; c < NCHUNK - 2; c++) {
        asm volatile("cp.async.wait_group 2;" ::: "memory");
        __syncthreads();
        if (c + 3 < NCHUNK) load_stage(sbase, (c + 3) & 3, c + 3, bm0, bn0, tid);
        uint32_t aB = sbase + (c & 3) * STAGE_B;
        compute_chunk(aB, aB + A_BYTES, acc, wm, wn, rl, ch);
    }
    // tail: fewer groups pending, so the waits must tighten (wait_group 2 with
    // only 2 pending groups would NOT guarantee the needed chunk is resident)
    {
        asm volatile("cp.async.wait_group 1;" ::: "memory");
        __syncthreads();
        uint32_t aB = sbase + ((NCHUNK - 2) & 3) * STAGE_B;
        compute_chunk(aB, aB + A_BYTES, acc, wm, wn, rl, ch);
    }
    {
        asm volatile("cp.async.wait_group 0;" ::: "memory");
        __syncthreads();
        uint32_t aB = sbase + ((NCHUNK - 1) & 3) * STAGE_B;
        compute_chunk(aB, aB + A_BYTES, acc, wm, wn, rl, ch);
    }

    // ----- epilogue: exp + label mask + row sums -----
    const int g  = lane >> 2;
    const int t4 = lane & 3;

    int rowlab[8];
    #pragma unroll
    for (int i = 0; i < 4; i++) {
        rowlab[2 * i + 0] = sla[wm * 64 + i * 16 + g];
        rowlab[2 * i + 1] = sla[wm * 64 + i * 16 + g + 8];
    }
    int collab[16];
    #pragma unroll
    for (int j = 0; j < 8; j++) {
        collab[2 * j + 0] = slb[wn * 64 + j * 8 + t4 * 2 + 0];
        collab[2 * j + 1] = slb[wn * 64 + j * 8 + t4 * 2 + 1];
    }

    float prow[8], nrow[8];
    #pragma unroll
    for (int k = 0; k < 8; k++) { prow[k] = 0.0f; nrow[k] = 0.0f; }

    #pragma unroll
    for (int i = 0; i < 4; i++)
        #pragma unroll
        for (int j = 0; j < 8; j++)
            #pragma unroll
            for (int v = 0; v < 4; v++) {
                float sim = acc[i][j][v] * kTempInv;
                sim = fminf(fmaxf(sim, -50.0f), 50.0f);
                float e = __expf(sim);
                int h = v >> 1;
                nrow[2 * i + h] += e;
                if (collab[2 * j + (v & 1)] == rowlab[2 * i + h])
                    prow[2 * i + h] += e;
            }

    // reduce across the 4 lanes of each quad (same row, different cols)
    #pragma unroll
    for (int off = 1; off <= 2; off <<= 1)
        #pragma unroll
        for (int k = 0; k < 8; k++) {
            prow[k] += __shfl_xor_sync(0xffffffffu, prow[k], off);
            nrow[k] += __shfl_xor_sync(0xffffffffu, nrow[k], off);
        }

    if (t4 == 0) {
        #pragma unroll
        for (int k = 0; k < 8; k++) {
            int row = wm * 64 + (k >> 1) * 16 + g + (k & 1) * 8;
            atomicAdd(&spos[row], prow[k]);
            atomicAdd(&sneg[row], nrow[k]);
        }
    }
    __syncthreads();
    if (tid < BM) {
        atomicAdd(&g_pos[bm0 + tid], (double)spos[tid]);
        atomicAdd(&g_neg[bm0 + tid], (double)sneg[tid]);
    }
}

// ---------------------------------------------------------------------------
// finalize stage 1: 16 blocks x 512 threads, partial sums -> atomic double
// ---------------------------------------------------------------------------
__global__ void finalize1_kernel() {
    int t = blockIdx.x * blockDim.x + threadIdx.x;  // 8192 threads total
    double p = g_pos[t];
    if (p < 1e-8) p = 1e-8;
    double local = (double)logf((float)(p / g_neg[t]));
    #pragma unroll
    for (int off = 16; off > 0; off >>= 1)
        local += __shfl_xor_sync(0xffffffffu, local, off);
    __shared__ double ws[16];
    int lt = threadIdx.x;
    if ((lt & 31) == 0) ws[lt >> 5] = local;
    __syncthreads();
    if (lt < 16) {
        double x = ws[lt];
        #pragma unroll
        for (int off = 8; off > 0; off >>= 1)
            x += __shfl_xor_sync(0xffffffffu, x, off);
        if (lt == 0) atomicAdd(&g_loss, x);
    }
}

__global__ void finalize2_kernel(float* __restrict__ out) {
    out[0] = (float)(-g_loss / (double)NROWS);
}

// ---------------------------------------------------------------------------
extern "C" void kernel_launch(void* const* d_in, const int* in_sizes, int n_in,
                              void* d_out, int out_size) {
    const float* fa = (const float*)d_in[0];
    const float* fb = (const float*)d_in[1];
    const int*   la = (const int*)d_in[2];
    const int*   lb = (const int*)d_in[3];
    float* out = (float*)d_out;

    cudaFuncSetAttribute(gemm_mma_kernel,
                         cudaFuncAttributeMaxDynamicSharedMemorySize, SMEM_TOTAL);

    zero_kernel<<<(NROWS + 255) / 256, 256>>>();
    normalize_kernel<<<2 * NROWS, 256>>>(fa, fb);
    dim3 grid(NROWS / BN, NROWS / BM);
    gemm_mma_kernel<<<grid, THREADS, SMEM_TOTAL>>>(la, lb);
    finalize1_kernel<<<16, 512>>>();
    finalize2_kernel<<<1, 1>>>(out);
}

// round 8
// speedup vs baseline: 8.4148x; 1.1050x over previous
#include <cuda_runtime.h>
#include <cuda_fp16.h>
#include <cstdint>
#include <math.h>

// ---------------- problem constants ----------------
#define NROWS 8192
#define DDIM  1024
#define BM 128
#define BN 128
#define BK 64                 // k elems per chunk = 128 bytes/row
#define NCHUNK (DDIM / BK)    // 16
#define NSTAGE 3
#define THREADS 256

static __device__ __constant__ float kTempInv = 14.2857142857142857f;  // 1/0.07

// ---------------- scratch (no runtime allocation) ----------------
__device__ __half g_fa[(size_t)NROWS * DDIM];   // normalized A, fp16
__device__ __half g_fb[(size_t)NROWS * DDIM];   // normalized B, fp16
__device__ double g_pos[NROWS];
__device__ double g_neg[NROWS];
__device__ double g_loss;

// ---------------- SMEM layout ----------------
#define A_BYTES (BM * 128)            // 16384
#define B_BYTES (BN * 128)            // 16384
#define STAGE_B (A_BYTES + B_BYTES)   // 32768
#define AUX_BASE (NSTAGE * STAGE_B)   // 98304
#define AUX_SLA  (AUX_BASE)           // 128*4
#define AUX_SLB  (AUX_BASE + 512)     // 128*4
#define AUX_SPOS (AUX_BASE + 1024)    // 128*4
#define AUX_SNEG (AUX_BASE + 1536)    // 128*4
#define SMEM_TOTAL (AUX_BASE + 2048)  // 100352  (x2 CTAs = 200704 <= 228KB)

#define SWZ(o) ((o) ^ (((o) >> 3) & 0x70))

__device__ __forceinline__ uint32_t smem_u32(const void* p) {
    uint32_t a;
    asm("{ .reg .u64 t; cvta.to.shared.u64 t, %1; cvt.u32.u64 %0, t; }"
        : "=r"(a) : "l"(p));
    return a;
}

#define LDSM_X4(r0, r1, r2, r3, addr) \
    asm volatile("ldmatrix.sync.aligned.m8n8.x4.shared.b16 {%0,%1,%2,%3}, [%4];" \
                 : "=r"(r0), "=r"(r1), "=r"(r2), "=r"(r3) : "r"(addr))

#define MMA16816(c, a, b0, b1) \
    asm volatile("mma.sync.aligned.m16n8k16.row.col.f32.f16.f16.f32 " \
                 "{%0,%1,%2,%3}, {%4,%5,%6,%7}, {%8,%9}, {%0,%1,%2,%3};" \
                 : "+f"((c)[0]), "+f"((c)[1]), "+f"((c)[2]), "+f"((c)[3]) \
                 : "r"((a)[0]), "r"((a)[1]), "r"((a)[2]), "r"((a)[3]), \
                   "r"(b0), "r"(b1))

#define CP_ASYNC16(dst, src) \
    asm volatile("cp.async.cg.shared.global [%0], [%1], 16;" :: "r"(dst), "l"(src))
#define CP_COMMIT() asm volatile("cp.async.commit_group;" ::: "memory")

// ---------------------------------------------------------------------------
__global__ void zero_kernel() {
    int i = blockIdx.x * blockDim.x + threadIdx.x;
    if (i < NROWS) { g_pos[i] = 0.0; g_neg[i] = 0.0; }
    if (i == 0) g_loss = 0.0;
}

// ---------------------------------------------------------------------------
// L2 normalize + fp16 convert. 2*NROWS blocks, 256 threads, 4 floats/thread.
// ---------------------------------------------------------------------------
__global__ void normalize_kernel(const float* __restrict__ A,
                                 const float* __restrict__ B) {
    int row = blockIdx.x;
    const float* src;
    __half* dst;
    if (row < NROWS) {
        src = A + (size_t)row * DDIM;
        dst = g_fa + (size_t)row * DDIM;
    } else {
        int r = row - NROWS;
        src = B + (size_t)r * DDIM;
        dst = g_fb + (size_t)r * DDIM;
    }
    int t = threadIdx.x;
    float4 v = reinterpret_cast<const float4*>(src)[t];
    float s = v.x * v.x + v.y * v.y + v.z * v.z + v.w * v.w;
    #pragma unroll
    for (int off = 16; off > 0; off >>= 1)
        s += __shfl_xor_sync(0xffffffffu, s, off);
    __shared__ float ws[8];
    if ((t & 31) == 0) ws[t >> 5] = s;
    __syncthreads();
    if (t < 32) {
        float x = (t < 8) ? ws[t] : 0.0f;
        #pragma unroll
        for (int off = 4; off > 0; off >>= 1)
            x += __shfl_xor_sync(0xffffffffu, x, off);
        if (t == 0) ws[0] = x;
    }
    __syncthreads();
    float scale = 1.0f / fmaxf(sqrtf(ws[0]), 1e-12f);

    __half2 h0 = __floats2half2_rn(v.x * scale, v.y * scale);
    __half2 h1 = __floats2half2_rn(v.z * scale, v.w * scale);
    __half2* p = reinterpret_cast<__half2*>(dst + t * 4);
    p[0] = h0;
    p[1] = h1;
}

// ---------------------------------------------------------------------------
// fp16 mma.sync GEMM (128x128 CTA tile, 2 CTAs/SM) + fused exp/mask epilogue
// ---------------------------------------------------------------------------
extern __shared__ __align__(1024) char smem[];

__device__ __forceinline__ void load_stage(uint32_t sbase, int s, int c,
                                           int bm0, int bn0, int tid) {
    uint32_t aB = sbase + s * STAGE_B;
    uint32_t bB = aB + A_BYTES;
    const int k0 = c * BK;
    #pragma unroll
    for (int it = 0; it < 4; it++) {          // A: 128 rows x 8 chunks of 16B
        int idx = tid + it * THREADS;
        int r = idx >> 3, u = idx & 7;
        const void* src = g_fa + (size_t)(bm0 + r) * DDIM + k0 + u * 8;
        CP_ASYNC16(aB + SWZ(r * 128 + u * 16), src);
    }
    #pragma unroll
    for (int it = 0; it < 4; it++) {          // B: 128 rows x 8 chunks of 16B
        int idx = tid + it * THREADS;
        int r = idx >> 3, u = idx & 7;
        const void* src = g_fb + (size_t)(bn0 + r) * DDIM + k0 + u * 8;
        CP_ASYNC16(bB + SWZ(r * 128 + u * 16), src);
    }
    CP_COMMIT();
}

// warp tile 32(M) x 64(N): wm = wid>>1 (0..3), wn = wid&1 (0..1)
__device__ __forceinline__ void compute_chunk(uint32_t aB, uint32_t bB,
                                              float (&acc)[2][8][4],
                                              int wm, int wn, int rl, int ch) {
    #pragma unroll
    for (int ks = 0; ks < 4; ks++) {
        const int cb = ks * 32 + ch * 16;
        uint32_t a[2][4];
        #pragma unroll
        for (int i = 0; i < 2; i++) {
            int row = wm * 32 + i * 16 + rl;
            LDSM_X4(a[i][0], a[i][1], a[i][2], a[i][3],
                    aB + SWZ(row * 128 + cb));
        }
        #pragma unroll
        for (int jj = 0; jj < 4; jj++) {
            int row = wn * 64 + jj * 16 + rl;
            uint32_t b0, b1, b2, b3;
            LDSM_X4(b0, b1, b2, b3, bB + SWZ(row * 128 + cb));
            #pragma unroll
            for (int i = 0; i < 2; i++) {
                MMA16816(acc[i][jj * 2 + 0], a[i], b0, b2);
                MMA16816(acc[i][jj * 2 + 1], a[i], b1, b3);
            }
        }
    }
}

__global__ __launch_bounds__(THREADS, 2)
void gemm_mma_kernel(const int* __restrict__ la, const int* __restrict__ lb) {
    const int tid  = threadIdx.x;
    const int lane = tid & 31;
    const int wid  = tid >> 5;
    const int wm   = wid >> 1;       // 4 warps along M
    const int wn   = wid & 1;        // 2 warps along N
    const int bm0  = blockIdx.y * BM;
    const int bn0  = blockIdx.x * BN;

    int* sla = (int*)(smem + AUX_SLA);
    int* slb = (int*)(smem + AUX_SLB);
    float* spos = (float*)(smem + AUX_SPOS);
    float* sneg = (float*)(smem + AUX_SNEG);

    if (tid < BM) {
        sla[tid] = la[bm0 + tid];
        slb[tid] = lb[bn0 + tid];
        spos[tid] = 0.0f;
        sneg[tid] = 0.0f;
    }

    uint32_t sbase = smem_u32(smem);

    float acc[2][8][4];
    #pragma unroll
    for (int i = 0; i < 2; i++)
        #pragma unroll
        for (int j = 0; j < 8; j++)
            #pragma unroll
            for (int v = 0; v < 4; v++)
                acc[i][j][v] = 0.0f;

    // prologue: 2 chunks in flight
    load_stage(sbase, 0, 0, bm0, bn0, tid);
    load_stage(sbase, 1, 1, bm0, bn0, tid);

    const int rl = lane & 15;
    const int ch = lane >> 4;

    // one sync per chunk; prefetch depth 2 over 3 buffers.
    // iter c: pending groups {c, c+1}; wait_group 1 retires chunk c.
    // chunk c+2 -> buffer (c+2)%3 == buffer consumed at iter c-1 (safe past sync).
    #pragma unroll 1
    for (int c = 0; c < NCHUNK - 1; c++) {
        asm volatile("cp.async.wait_group 1;" ::: "memory");
        __syncthreads();
        if (c + 2 < NCHUNK)
            load_stage(sbase, (c + 2) % NSTAGE, c + 2, bm0, bn0, tid);
        uint32_t aB = sbase + (c % NSTAGE) * STAGE_B;
        compute_chunk(aB, aB + A_BYTES, acc, wm, wn, rl, ch);
    }
    {   // last chunk: only group {15} pending
        asm volatile("cp.async.wait_group 0;" ::: "memory");
        __syncthreads();
        uint32_t aB = sbase + ((NCHUNK - 1) % NSTAGE) * STAGE_B;
        compute_chunk(aB, aB + A_BYTES, acc, wm, wn, rl, ch);
    }

    // ----- epilogue: exp + label mask + row sums -----
    const int g  = lane >> 2;
    const int t4 = lane & 3;

    int rowlab[4];
    #pragma unroll
    for (int i = 0; i < 2; i++) {
        rowlab[2 * i + 0] = sla[wm * 32 + i * 16 + g];
        rowlab[2 * i + 1] = sla[wm * 32 + i * 16 + g + 8];
    }
    int collab[16];
    #pragma unroll
    for (int j = 0; j < 8; j++) {
        collab[2 * j + 0] = slb[wn * 64 + j * 8 + t4 * 2 + 0];
        collab[2 * j + 1] = slb[wn * 64 + j * 8 + t4 * 2 + 1];
    }

    float prow[4], nrow[4];
    #pragma unroll
    for (int k = 0; k < 4; k++) { prow[k] = 0.0f; nrow[k] = 0.0f; }

    #pragma unroll
    for (int i = 0; i < 2; i++)
        #pragma unroll
        for (int j = 0; j < 8; j++)
            #pragma unroll
            for (int v = 0; v < 4; v++) {
                float sim = acc[i][j][v] * kTempInv;
                sim = fminf(fmaxf(sim, -50.0f), 50.0f);
                float e = __expf(sim);
                int h = v >> 1;
                nrow[2 * i + h] += e;
                if (collab[2 * j + (v & 1)] == rowlab[2 * i + h])
                    prow[2 * i + h] += e;
            }

    // reduce across the 4 lanes of each quad (same row, different cols)
    #pragma unroll
    for (int off = 1; off <= 2; off <<= 1)
        #pragma unroll
        for (int k = 0; k < 4; k++) {
            prow[k] += __shfl_xor_sync(0xffffffffu, prow[k], off);
            nrow[k] += __shfl_xor_sync(0xffffffffu, nrow[k], off);
        }

    if (t4 == 0) {
        #pragma unroll
        for (int k = 0; k < 4; k++) {
            int row = wm * 32 + (k >> 1) * 16 + g + (k & 1) * 8;
            atomicAdd(&spos[row], prow[k]);
            atomicAdd(&sneg[row], nrow[k]);
        }
    }
    __syncthreads();
    if (tid < BM) {
        atomicAdd(&g_pos[bm0 + tid], (double)spos[tid]);
        atomicAdd(&g_neg[bm0 + tid], (double)sneg[tid]);
    }
}

// ---------------------------------------------------------------------------
// finalize stage 1: 16 blocks x 512 threads, partial sums -> atomic double
// ---------------------------------------------------------------------------
__global__ void finalize1_kernel() {
    int t = blockIdx.x * blockDim.x + threadIdx.x;  // 8192 threads total
    double p = g_pos[t];
    if (p < 1e-8) p = 1e-8;
    double local = (double)logf((float)(p / g_neg[t]));
    #pragma unroll
    for (int off = 16; off > 0; off >>= 1)
        local += __shfl_xor_sync(0xffffffffu, local, off);
    __shared__ double ws[16];
    int lt = threadIdx.x;
    if ((lt & 31) == 0) ws[lt >> 5] = local;
    __syncthreads();
    if (lt < 16) {
        double x = ws[lt];
        #pragma unroll
        for (int off = 8; off > 0; off >>= 1)
            x += __shfl_xor_sync(0xffffffffu, x, off);
        if (lt == 0) atomicAdd(&g_loss, x);
    }
}

__global__ void finalize2_kernel(float* __restrict__ out) {
    out[0] = (float)(-g_loss / (double)NROWS);
}

// ---------------------------------------------------------------------------
extern "C" void kernel_launch(void* const* d_in, const int* in_sizes, int n_in,
                              void* d_out, int out_size) {
    const float* fa = (const float*)d_in[0];
    const float* fb = (const float*)d_in[1];
    const int*   la = (const int*)d_in[2];
    const int*   lb = (const int*)d_in[3];
    float* out = (float*)d_out;

    cudaFuncSetAttribute(gemm_mma_kernel,
                         cudaFuncAttributeMaxDynamicSharedMemorySize, SMEM_TOTAL);

    zero_kernel<<<(NROWS + 255) / 256, 256>>>();
    normalize_kernel<<<2 * NROWS, 256>>>(fa, fb);
    dim3 grid(NROWS / BN, NROWS / BM);
    gemm_mma_kernel<<<grid, THREADS, SMEM_TOTAL>>>(la, lb);
    finalize1_kernel<<<16, 512>>>();
    finalize2_kernel<<<1, 1>>>(out);
}

// round 10
// speedup vs baseline: 8.4431x; 1.0034x over previous
#include <cuda_runtime.h>
#include <cuda_fp16.h>
#include <cstdint>
#include <math.h>

// ---------------- problem constants ----------------
#define NROWS 8192
#define DDIM  1024
#define BM 128
#define BN 128
#define BK 64                 // k elems per chunk = 128 bytes/row
#define NCHUNK (DDIM / BK)    // 16
#define NSTAGE 3
#define THREADS 256

static __device__ __constant__ float kTempInv = 14.2857142857142857f;  // 1/0.07

// ---------------- scratch (no runtime allocation) ----------------
__device__ __half g_fa[(size_t)NROWS * DDIM];   // normalized A, fp16
__device__ __half g_fb[(size_t)NROWS * DDIM];   // normalized B, fp16
__device__ double g_pos[NROWS];
__device__ double g_neg[NROWS];
__device__ double g_loss;

// ---------------- SMEM layout ----------------
#define A_BYTES (BM * 128)            // 16384
#define B_BYTES (BN * 128)            // 16384
#define STAGE_B (A_BYTES + B_BYTES)   // 32768
#define AUX_BASE (NSTAGE * STAGE_B)   // 98304
#define AUX_SLA  (AUX_BASE)           // 128*4
#define AUX_SLB  (AUX_BASE + 512)     // 128*4
#define AUX_SPOS (AUX_BASE + 1024)    // 128*4
#define AUX_SNEG (AUX_BASE + 1536)    // 128*4
#define SMEM_TOTAL (AUX_BASE + 2048)  // 100352  (x2 CTAs = 200704 <= 228KB)

#define SWZ(o) ((o) ^ (((o) >> 3) & 0x70))

__device__ __forceinline__ uint32_t smem_u32(const void* p) {
    uint32_t a;
    asm("{ .reg .u64 t; cvta.to.shared.u64 t, %1; cvt.u32.u64 %0, t; }"
        : "=r"(a) : "l"(p));
    return a;
}

#define LDSM_X4(r0, r1, r2, r3, addr) \
    asm volatile("ldmatrix.sync.aligned.m8n8.x4.shared.b16 {%0,%1,%2,%3}, [%4];" \
                 : "=r"(r0), "=r"(r1), "=r"(r2), "=r"(r3) : "r"(addr))

#define MMA16816(c, a, b0, b1) \
    asm volatile("mma.sync.aligned.m16n8k16.row.col.f32.f16.f16.f32 " \
                 "{%0,%1,%2,%3}, {%4,%5,%6,%7}, {%8,%9}, {%0,%1,%2,%3};" \
                 : "+f"((c)[0]), "+f"((c)[1]), "+f"((c)[2]), "+f"((c)[3]) \
                 : "r"((a)[0]), "r"((a)[1]), "r"((a)[2]), "r"((a)[3]), \
                   "r"(b0), "r"(b1))

#define CP_ASYNC16(dst, src) \
    asm volatile("cp.async.cg.shared.global [%0], [%1], 16;" :: "r"(dst), "l"(src))
#define CP_COMMIT() asm volatile("cp.async.commit_group;" ::: "memory")

// ---------------------------------------------------------------------------
// L2 normalize + fp16 convert + accumulator zeroing (no separate zero_kernel).
// 2*NROWS blocks, 256 threads, 4 floats/thread.
// ---------------------------------------------------------------------------
__global__ void normalize_kernel(const float* __restrict__ A,
                                 const float* __restrict__ B) {
    int row = blockIdx.x;
    const float* src;
    __half* dst;
    if (row < NROWS) {
        src = A + (size_t)row * DDIM;
        dst = g_fa + (size_t)row * DDIM;
        if (threadIdx.x == 0) { g_pos[row] = 0.0; g_neg[row] = 0.0; }
        if (row == 0 && threadIdx.x == 1) g_loss = 0.0;
    } else {
        int r = row - NROWS;
        src = B + (size_t)r * DDIM;
        dst = g_fb + (size_t)r * DDIM;
    }
    int t = threadIdx.x;
    float4 v = reinterpret_cast<const float4*>(src)[t];
    float s = v.x * v.x + v.y * v.y + v.z * v.z + v.w * v.w;
    #pragma unroll
    for (int off = 16; off > 0; off >>= 1)
        s += __shfl_xor_sync(0xffffffffu, s, off);
    __shared__ float ws[8];
    if ((t & 31) == 0) ws[t >> 5] = s;
    __syncthreads();
    if (t < 32) {
        float x = (t < 8) ? ws[t] : 0.0f;
        #pragma unroll
        for (int off = 4; off > 0; off >>= 1)
            x += __shfl_xor_sync(0xffffffffu, x, off);
        if (t == 0) ws[0] = x;
    }
    __syncthreads();
    float scale = 1.0f / fmaxf(sqrtf(ws[0]), 1e-12f);

    __half2 h0 = __floats2half2_rn(v.x * scale, v.y * scale);
    __half2 h1 = __floats2half2_rn(v.z * scale, v.w * scale);
    __half2* p = reinterpret_cast<__half2*>(dst + t * 4);
    p[0] = h0;
    p[1] = h1;
}

// ---------------------------------------------------------------------------
// fp16 mma.sync GEMM (128x128 CTA tile, 2 CTAs/SM) + fused exp/mask epilogue
// ---------------------------------------------------------------------------
extern __shared__ __align__(1024) char smem[];

__device__ __forceinline__ void load_stage(uint32_t dstA, uint32_t dstB,
                                           const __half* srcA,
                                           const __half* srcB) {
    // 4 x 16B per matrix per thread; offsets precomputed by caller.
    #pragma unroll
    for (int it = 0; it < 4; it++)
        CP_ASYNC16(dstA + it * 4096, srcA + (size_t)it * 32 * DDIM);
    #pragma unroll
    for (int it = 0; it < 4; it++)
        CP_ASYNC16(dstB + it * 4096, srcB + (size_t)it * 32 * DDIM);
    CP_COMMIT();
}

// warp tile 32(M) x 64(N): wm = wid>>1 (0..3), wn = wid&1 (0..1)
__device__ __forceinline__ void compute_chunk(uint32_t aBase0, uint32_t aBase1,
                                              uint32_t bBase0, uint32_t bBase1,
                                              uint32_t bBase2, uint32_t bBase3,
                                              float (&acc)[2][8][4]) {
    #pragma unroll
    for (int ks = 0; ks < 4; ks++) {
        const uint32_t cb = ks * 32;   // XOR-offset within swizzled row
        uint32_t a[2][4];
        LDSM_X4(a[0][0], a[0][1], a[0][2], a[0][3], aBase0 ^ cb);
        LDSM_X4(a[1][0], a[1][1], a[1][2], a[1][3], aBase1 ^ cb);
        uint32_t b0, b1, b2, b3;
        LDSM_X4(b0, b1, b2, b3, bBase0 ^ cb);
        MMA16816(acc[0][0], a[0], b0, b2);
        MMA16816(acc[0][1], a[0], b1, b3);
        MMA16816(acc[1][0], a[1], b0, b2);
        MMA16816(acc[1][1], a[1], b1, b3);
        LDSM_X4(b0, b1, b2, b3, bBase1 ^ cb);
        MMA16816(acc[0][2], a[0], b0, b2);
        MMA16816(acc[0][3], a[0], b1, b3);
        MMA16816(acc[1][2], a[1], b0, b2);
        MMA16816(acc[1][3], a[1], b1, b3);
        LDSM_X4(b0, b1, b2, b3, bBase2 ^ cb);
        MMA16816(acc[0][4], a[0], b0, b2);
        MMA16816(acc[0][5], a[0], b1, b3);
        MMA16816(acc[1][4], a[1], b0, b2);
        MMA16816(acc[1][5], a[1], b1, b3);
        LDSM_X4(b0, b1, b2, b3, bBase3 ^ cb);
        MMA16816(acc[0][6], a[0], b0, b2);
        MMA16816(acc[0][7], a[0], b1, b3);
        MMA16816(acc[1][6], a[1], b0, b2);
        MMA16816(acc[1][7], a[1], b1, b3);
    }
}

__global__ __launch_bounds__(THREADS, 2)
void gemm_mma_kernel(const int* __restrict__ la, const int* __restrict__ lb) {
    const int tid  = threadIdx.x;
    const int lane = tid & 31;
    const int wid  = tid >> 5;
    const int wm   = wid >> 1;       // 4 warps along M
    const int wn   = wid & 1;        // 2 warps along N
    const int bm0  = blockIdx.y * BM;
    const int bn0  = blockIdx.x * BN;

    int* sla = (int*)(smem + AUX_SLA);
    int* slb = (int*)(smem + AUX_SLB);
    float* spos = (float*)(smem + AUX_SPOS);
    float* sneg = (float*)(smem + AUX_SNEG);

    if (tid < BM) {
        sla[tid] = la[bm0 + tid];
        slb[tid] = lb[bn0 + tid];
        spos[tid] = 0.0f;
        sneg[tid] = 0.0f;
    }

    uint32_t sbase = smem_u32(smem);

    // ---- per-thread cp.async offsets (row = tid>>3 in [0,32), u = tid&7) ----
    const int ld_r = tid >> 3;
    const int ld_u = tid & 7;
    const uint32_t ld_off = SWZ(ld_r * 128 + ld_u * 16);
    const __half* srcA = g_fa + (size_t)(bm0 + ld_r) * DDIM + ld_u * 8;
    const __half* srcB = g_fb + (size_t)(bn0 + ld_r) * DDIM + ld_u * 8;

    // ---- per-thread ldsm base addresses ----
    // SWZ(row*128 + cb) == row*128 + (cb ^ (row&7)*16) for cb in bits [4:7)
    const int rl = lane & 15;
    const int ch = lane >> 4;
    const int ar0 = wm * 32 + rl;
    const int ar1 = wm * 32 + 16 + rl;
    const int br0 = wn * 64 + rl;
    const uint32_t chx = (uint32_t)(ch * 16);
    const uint32_t aOff0 = (uint32_t)(ar0 * 128) + (((uint32_t)(ar0 & 7) * 16) ^ chx);
    const uint32_t aOff1 = (uint32_t)(ar1 * 128) + (((uint32_t)(ar1 & 7) * 16) ^ chx);
    const uint32_t bOff0 = (uint32_t)(br0 * 128) + (((uint32_t)(br0 & 7) * 16) ^ chx);
    const uint32_t bStep = 16 * 128;   // row&7 repeats every 16 rows

    float acc[2][8][4];
    #pragma unroll
    for (int i = 0; i < 2; i++)
        #pragma unroll
        for (int j = 0; j < 8; j++)
            #pragma unroll
            for (int v = 0; v < 4; v++)
                acc[i][j][v] = 0.0f;

    // prologue: 2 chunks in flight
    load_stage(sbase + ld_off, sbase + A_BYTES + ld_off, srcA, srcB);
    load_stage(sbase + STAGE_B + ld_off, sbase + STAGE_B + A_BYTES + ld_off,
               srcA + BK, srcB + BK);

    // one sync per chunk; prefetch depth 2 over 3 buffers.
    // iter c: pending groups {c, c+1}; wait_group 1 retires chunk c.
    // chunk c+2 -> buffer (c+2)%3 == buffer consumed at iter c-1 (safe past sync).
    #pragma unroll 1
    for (int c = 0; c < NCHUNK - 1; c++) {
        asm volatile("cp.async.wait_group 1;" ::: "memory");
        __syncthreads();
        if (c + 2 < NCHUNK) {
            uint32_t st = ((c + 2) % NSTAGE) * STAGE_B;
            load_stage(sbase + st + ld_off, sbase + st + A_BYTES + ld_off,
                       srcA + (c + 2) * BK, srcB + (c + 2) * BK);
        }
        uint32_t aB = sbase + (c % NSTAGE) * STAGE_B;
        uint32_t bB = aB + A_BYTES;
        compute_chunk(aB + aOff0, aB + aOff1,
                      bB + bOff0, bB + bOff0 + bStep,
                      bB + bOff0 + 2 * bStep, bB + bOff0 + 3 * bStep, acc);
    }
    {   // last chunk: only one group pending
        asm volatile("cp.async.wait_group 0;" ::: "memory");
        __syncthreads();
        uint32_t aB = sbase + ((NCHUNK - 1) % NSTAGE) * STAGE_B;
        uint32_t bB = aB + A_BYTES;
        compute_chunk(aB + aOff0, aB + aOff1,
                      bB + bOff0, bB + bOff0 + bStep,
                      bB + bOff0 + 2 * bStep, bB + bOff0 + 3 * bStep, acc);
    }

    // ----- epilogue: exp + label mask + row sums -----
    const int g  = lane >> 2;
    const int t4 = lane & 3;

    int rowlab[4];
    #pragma unroll
    for (int i = 0; i < 2; i++) {
        rowlab[2 * i + 0] = sla[wm * 32 + i * 16 + g];
        rowlab[2 * i + 1] = sla[wm * 32 + i * 16 + g + 8];
    }
    int collab[16];
    #pragma unroll
    for (int j = 0; j < 8; j++) {
        collab[2 * j + 0] = slb[wn * 64 + j * 8 + t4 * 2 + 0];
        collab[2 * j + 1] = slb[wn * 64 + j * 8 + t4 * 2 + 1];
    }

    float prow[4], nrow[4];
    #pragma unroll
    for (int k = 0; k < 4; k++) { prow[k] = 0.0f; nrow[k] = 0.0f; }

    #pragma unroll
    for (int i = 0; i < 2; i++)
        #pragma unroll
        for (int j = 0; j < 8; j++)
            #pragma unroll
            for (int v = 0; v < 4; v++) {
                float sim = acc[i][j][v] * kTempInv;
                sim = fminf(fmaxf(sim, -50.0f), 50.0f);
                float e = __expf(sim);
                int h = v >> 1;
                nrow[2 * i + h] += e;
                if (collab[2 * j + (v & 1)] == rowlab[2 * i + h])
                    prow[2 * i + h] += e;
            }

    // reduce across the 4 lanes of each quad (same row, different cols)
    #pragma unroll
    for (int off = 1; off <= 2; off <<= 1)
        #pragma unroll
        for (int k = 0; k < 4; k++) {
            prow[k] += __shfl_xor_sync(0xffffffffu, prow[k], off);
            nrow[k] += __shfl_xor_sync(0xffffffffu, nrow[k], off);
        }

    if (t4 == 0) {
        #pragma unroll
        for (int k = 0; k < 4; k++) {
            int row = wm * 32 + (k >> 1) * 16 + g + (k & 1) * 8;
            atomicAdd(&spos[row], prow[k]);
            atomicAdd(&sneg[row], nrow[k]);
        }
    }
    __syncthreads();
    if (tid < BM) {
        atomicAdd(&g_pos[bm0 + tid], (double)spos[tid]);
        atomicAdd(&g_neg[bm0 + tid], (double)sneg[tid]);
    }
}

// ---------------------------------------------------------------------------
// finalize stage 1: 16 blocks x 512 threads, partial sums -> atomic double
// ---------------------------------------------------------------------------
__global__ void finalize1_kernel() {
    int t = blockIdx.x * blockDim.x + threadIdx.x;  // 8192 threads total
    double p = g_pos[t];
    if (p < 1e-8) p = 1e-8;
    double local = (double)logf((float)(p / g_neg[t]));
    #pragma unroll
    for (int off = 16; off > 0; off >>= 1)
        local += __shfl_xor_sync(0xffffffffu, local, off);
    __shared__ double ws[16];
    int lt = threadIdx.x;
    if ((lt & 31) == 0) ws[lt >> 5] = local;
    __syncthreads();
    if (lt < 16) {
        double x = ws[lt];
        #pragma unroll
        for (int off = 8; off > 0; off >>= 1)
            x += __shfl_xor_sync(0xffffffffu, x, off);
        if (lt == 0) atomicAdd(&g_loss, x);
    }
}

__global__ void finalize2_kernel(float* __restrict__ out) {
    out[0] = (float)(-g_loss / (double)NROWS);
}

// ---------------------------------------------------------------------------
extern "C" void kernel_launch(void* const* d_in, const int* in_sizes, int n_in,
                              void* d_out, int out_size) {
    const float* fa = (const float*)d_in[0];
    const float* fb = (const float*)d_in[1];
    const int*   la = (const int*)d_in[2];
    const int*   lb = (const int*)d_in[3];
    float* out = (float*)d_out;

    cudaFuncSetAttribute(gemm_mma_kernel,
                         cudaFuncAttributeMaxDynamicSharedMemorySize, SMEM_TOTAL);

    normalize_kernel<<<2 * NROWS, 256>>>(fa, fb);
    dim3 grid(NROWS / BN, NROWS / BM);
    gemm_mma_kernel<<<grid, THREADS, SMEM_TOTAL>>>(la, lb);
    finalize1_kernel<<<16, 512>>>();
    finalize2_kernel<<<1, 1>>>(out);
}

// round 11
// speedup vs baseline: 9.0104x; 1.0672x over previous
#include <cuda_runtime.h>
#include <cuda_fp16.h>
#include <cstdint>
#include <math.h>

// ---------------- problem constants ----------------
#define NROWS 8192
#define DDIM  1024
#define BM 128
#define BN 128
#define BK 64                 // k elems per chunk = 128 bytes/row
#define NCHUNK (DDIM / BK)    // 16
#define NSTAGE 3
#define THREADS 256

static __device__ __constant__ float kTempInv = 14.2857142857142857f;  // 1/0.07

// ---------------- scratch (no runtime allocation) ----------------
__device__ __half g_fa[(size_t)NROWS * DDIM];   // normalized A, fp16
__device__ __half g_fb[(size_t)NROWS * DDIM];   // normalized B, fp16
__device__ double g_pos[NROWS];
__device__ double g_neg[NROWS];
__device__ double g_loss;

// ---------------- SMEM layout ----------------
#define A_BYTES (BM * 128)            // 16384
#define B_BYTES (BN * 128)            // 16384
#define STAGE_B (A_BYTES + B_BYTES)   // 32768
#define AUX_BASE (NSTAGE * STAGE_B)   // 98304
#define AUX_SLA  (AUX_BASE)           // 128*4
#define AUX_SLB  (AUX_BASE + 512)     // 128*4
#define AUX_SPOS (AUX_BASE + 1024)    // 128*4
#define AUX_SNEG (AUX_BASE + 1536)    // 128*4
#define SMEM_TOTAL (AUX_BASE + 2048)  // 100352  (x2 CTAs = 200704 <= 228KB)

#define SWZ(o) ((o) ^ (((o) >> 3) & 0x70))

__device__ __forceinline__ uint32_t smem_u32(const void* p) {
    uint32_t a;
    asm("{ .reg .u64 t; cvta.to.shared.u64 t, %1; cvt.u32.u64 %0, t; }"
        : "=r"(a) : "l"(p));
    return a;
}

#define LDSM_X4(r0, r1, r2, r3, addr) \
    asm volatile("ldmatrix.sync.aligned.m8n8.x4.shared.b16 {%0,%1,%2,%3}, [%4];" \
                 : "=r"(r0), "=r"(r1), "=r"(r2), "=r"(r3) : "r"(addr))

#define MMA16816(c, a, b0, b1) \
    asm volatile("mma.sync.aligned.m16n8k16.row.col.f32.f16.f16.f32 " \
                 "{%0,%1,%2,%3}, {%4,%5,%6,%7}, {%8,%9}, {%0,%1,%2,%3};" \
                 : "+f"((c)[0]), "+f"((c)[1]), "+f"((c)[2]), "+f"((c)[3]) \
                 : "r"((a)[0]), "r"((a)[1]), "r"((a)[2]), "r"((a)[3]), \
                   "r"(b0), "r"(b1))

#define CP_ASYNC16(dst, src) \
    asm volatile("cp.async.cg.shared.global [%0], [%1], 16;" :: "r"(dst), "l"(src))
#define CP_COMMIT() asm volatile("cp.async.commit_group;" ::: "memory")

// ---------------------------------------------------------------------------
// L2 normalize + fp16 convert + accumulator zeroing.
// 2*NROWS blocks, 256 threads, 4 floats/thread.
// ---------------------------------------------------------------------------
__global__ void normalize_kernel(const float* __restrict__ A,
                                 const float* __restrict__ B) {
    int row = blockIdx.x;
    const float* src;
    __half* dst;
    if (row < NROWS) {
        src = A + (size_t)row * DDIM;
        dst = g_fa + (size_t)row * DDIM;
        if (threadIdx.x == 0) { g_pos[row] = 0.0; g_neg[row] = 0.0; }
        if (row == 0 && threadIdx.x == 1) g_loss = 0.0;
    } else {
        int r = row - NROWS;
        src = B + (size_t)r * DDIM;
        dst = g_fb + (size_t)r * DDIM;
    }
    int t = threadIdx.x;
    float4 v = reinterpret_cast<const float4*>(src)[t];
    float s = v.x * v.x + v.y * v.y + v.z * v.z + v.w * v.w;
    #pragma unroll
    for (int off = 16; off > 0; off >>= 1)
        s += __shfl_xor_sync(0xffffffffu, s, off);
    __shared__ float ws[8];
    if ((t & 31) == 0) ws[t >> 5] = s;
    __syncthreads();
    if (t < 32) {
        float x = (t < 8) ? ws[t] : 0.0f;
        #pragma unroll
        for (int off = 4; off > 0; off >>= 1)
            x += __shfl_xor_sync(0xffffffffu, x, off);
        if (t == 0) ws[0] = x;
    }
    __syncthreads();
    float scale = 1.0f / fmaxf(sqrtf(ws[0]), 1e-12f);

    __half2 h0 = __floats2half2_rn(v.x * scale, v.y * scale);
    __half2 h1 = __floats2half2_rn(v.z * scale, v.w * scale);
    __half2* p = reinterpret_cast<__half2*>(dst + t * 4);
    p[0] = h0;
    p[1] = h1;
}

// ---------------------------------------------------------------------------
// fp16 mma.sync GEMM (128x128 CTA tile, 2 CTAs/SM) + fused exp/mask epilogue
// Prefetch cp.asyncs are interleaved into the compute (2 per ks-step) to
// avoid post-barrier front-batched load bursts (cross-CTA L1tex contention).
// ---------------------------------------------------------------------------
extern __shared__ __align__(1024) char smem[];

// warp tile 32(M) x 64(N): wm = wid>>1 (0..3), wn = wid&1 (0..1)
template <bool PRE>
__device__ __forceinline__ void compute_chunk(uint32_t aBase0, uint32_t aBase1,
                                              uint32_t bBase0, uint32_t bBase1,
                                              uint32_t bBase2, uint32_t bBase3,
                                              float (&acc)[2][8][4],
                                              uint32_t dstA, uint32_t dstB,
                                              const __half* srcA,
                                              const __half* srcB) {
    #pragma unroll
    for (int ks = 0; ks < 4; ks++) {
        if (PRE) {  // 2 of the 8 prefetch cp.asyncs per ks-step
            CP_ASYNC16(dstA + ks * 4096, srcA + (size_t)ks * 32 * DDIM);
            CP_ASYNC16(dstB + ks * 4096, srcB + (size_t)ks * 32 * DDIM);
        }
        const uint32_t cb = ks * 32;   // XOR-offset within swizzled row
        uint32_t a[2][4];
        LDSM_X4(a[0][0], a[0][1], a[0][2], a[0][3], aBase0 ^ cb);
        LDSM_X4(a[1][0], a[1][1], a[1][2], a[1][3], aBase1 ^ cb);
        uint32_t b0, b1, b2, b3;
        LDSM_X4(b0, b1, b2, b3, bBase0 ^ cb);
        MMA16816(acc[0][0], a[0], b0, b2);
        MMA16816(acc[0][1], a[0], b1, b3);
        MMA16816(acc[1][0], a[1], b0, b2);
        MMA16816(acc[1][1], a[1], b1, b3);
        LDSM_X4(b0, b1, b2, b3, bBase1 ^ cb);
        MMA16816(acc[0][2], a[0], b0, b2);
        MMA16816(acc[0][3], a[0], b1, b3);
        MMA16816(acc[1][2], a[1], b0, b2);
        MMA16816(acc[1][3], a[1], b1, b3);
        LDSM_X4(b0, b1, b2, b3, bBase2 ^ cb);
        MMA16816(acc[0][4], a[0], b0, b2);
        MMA16816(acc[0][5], a[0], b1, b3);
        MMA16816(acc[1][4], a[1], b0, b2);
        MMA16816(acc[1][5], a[1], b1, b3);
        LDSM_X4(b0, b1, b2, b3, bBase3 ^ cb);
        MMA16816(acc[0][6], a[0], b0, b2);
        MMA16816(acc[0][7], a[0], b1, b3);
        MMA16816(acc[1][6], a[1], b0, b2);
        MMA16816(acc[1][7], a[1], b1, b3);
    }
    if (PRE) CP_COMMIT();
}

__global__ __launch_bounds__(THREADS, 2)
void gemm_mma_kernel(const int* __restrict__ la, const int* __restrict__ lb) {
    const int tid  = threadIdx.x;
    const int lane = tid & 31;
    const int wid  = tid >> 5;
    const int wm   = wid >> 1;       // 4 warps along M
    const int wn   = wid & 1;        // 2 warps along N
    const int bm0  = blockIdx.y * BM;
    const int bn0  = blockIdx.x * BN;

    int* sla = (int*)(smem + AUX_SLA);
    int* slb = (int*)(smem + AUX_SLB);
    float* spos = (float*)(smem + AUX_SPOS);
    float* sneg = (float*)(smem + AUX_SNEG);

    if (tid < BM) {
        sla[tid] = la[bm0 + tid];
        slb[tid] = lb[bn0 + tid];
        spos[tid] = 0.0f;
        sneg[tid] = 0.0f;
    }

    uint32_t sbase = smem_u32(smem);

    // ---- per-thread cp.async offsets (row = tid>>3 in [0,32), u = tid&7) ----
    const int ld_r = tid >> 3;
    const int ld_u = tid & 7;
    const uint32_t ld_off = SWZ(ld_r * 128 + ld_u * 16);
    const __half* srcA = g_fa + (size_t)(bm0 + ld_r) * DDIM + ld_u * 8;
    const __half* srcB = g_fb + (size_t)(bn0 + ld_r) * DDIM + ld_u * 8;

    // ---- per-thread ldsm base addresses ----
    // SWZ(row*128 + cb) == row*128 + (cb ^ (row&7)*16) for cb in bits [4:7)
    const int rl = lane & 15;
    const int ch = lane >> 4;
    const int ar0 = wm * 32 + rl;
    const int ar1 = wm * 32 + 16 + rl;
    const int br0 = wn * 64 + rl;
    const uint32_t chx = (uint32_t)(ch * 16);
    const uint32_t aOff0 = (uint32_t)(ar0 * 128) + (((uint32_t)(ar0 & 7) * 16) ^ chx);
    const uint32_t aOff1 = (uint32_t)(ar1 * 128) + (((uint32_t)(ar1 & 7) * 16) ^ chx);
    const uint32_t bOff0 = (uint32_t)(br0 * 128) + (((uint32_t)(br0 & 7) * 16) ^ chx);
    const uint32_t bStep = 16 * 128;   // row&7 repeats every 16 rows

    float acc[2][8][4];
    #pragma unroll
    for (int i = 0; i < 2; i++)
        #pragma unroll
        for (int j = 0; j < 8; j++)
            #pragma unroll
            for (int v = 0; v < 4; v++)
                acc[i][j][v] = 0.0f;

    // prologue: chunks 0 and 1 in flight (pipeline fill; bursts OK here)
    {
        uint32_t dA0 = sbase + ld_off, dB0 = sbase + A_BYTES + ld_off;
        #pragma unroll
        for (int it = 0; it < 4; it++) {
            CP_ASYNC16(dA0 + it * 4096, srcA + (size_t)it * 32 * DDIM);
            CP_ASYNC16(dB0 + it * 4096, srcB + (size_t)it * 32 * DDIM);
        }
        CP_COMMIT();
        uint32_t dA1 = dA0 + STAGE_B, dB1 = dB0 + STAGE_B;
        #pragma unroll
        for (int it = 0; it < 4; it++) {
            CP_ASYNC16(dA1 + it * 4096, srcA + BK + (size_t)it * 32 * DDIM);
            CP_ASYNC16(dB1 + it * 4096, srcB + BK + (size_t)it * 32 * DDIM);
        }
        CP_COMMIT();
    }

    // one sync per chunk; prefetch depth 2 over 3 buffers, loads interleaved
    // into compute. iter c: pending groups {c, c+1}; wait_group 1 retires c.
    // chunk c+2 -> buffer (c+2)%3 == buffer consumed at iter c-1 (all readers
    // passed this iteration's barrier).
    #pragma unroll 1
    for (int c = 0; c < NCHUNK - 2; c++) {
        asm volatile("cp.async.wait_group 1;" ::: "memory");
        __syncthreads();
        uint32_t aB = sbase + (c % NSTAGE) * STAGE_B;
        uint32_t bB = aB + A_BYTES;
        uint32_t st = ((c + 2) % NSTAGE) * STAGE_B;
        compute_chunk<true>(aB + aOff0, aB + aOff1,
                            bB + bOff0, bB + bOff0 + bStep,
                            bB + bOff0 + 2 * bStep, bB + bOff0 + 3 * bStep, acc,
                            sbase + st + ld_off, sbase + st + A_BYTES + ld_off,
                            srcA + (c + 2) * BK, srcB + (c + 2) * BK);
    }
    {   // chunk 14: pending {14, 15}
        asm volatile("cp.async.wait_group 1;" ::: "memory");
        __syncthreads();
        uint32_t aB = sbase + ((NCHUNK - 2) % NSTAGE) * STAGE_B;
        uint32_t bB = aB + A_BYTES;
        compute_chunk<false>(aB + aOff0, aB + aOff1,
                             bB + bOff0, bB + bOff0 + bStep,
                             bB + bOff0 + 2 * bStep, bB + bOff0 + 3 * bStep, acc,
                             0, 0, nullptr, nullptr);
    }
    {   // chunk 15: pending {15}
        asm volatile("cp.async.wait_group 0;" ::: "memory");
        __syncthreads();
        uint32_t aB = sbase + ((NCHUNK - 1) % NSTAGE) * STAGE_B;
        uint32_t bB = aB + A_BYTES;
        compute_chunk<false>(aB + aOff0, aB + aOff1,
                             bB + bOff0, bB + bOff0 + bStep,
                             bB + bOff0 + 2 * bStep, bB + bOff0 + 3 * bStep, acc,
                             0, 0, nullptr, nullptr);
    }

    // ----- epilogue: exp + label mask + row sums -----
    // NOTE: clip to [-50,50] omitted: |sim| <= 1/0.07 = 14.29 for unit rows.
    const int g  = lane >> 2;
    const int t4 = lane & 3;

    int rowlab[4];
    #pragma unroll
    for (int i = 0; i < 2; i++) {
        rowlab[2 * i + 0] = sla[wm * 32 + i * 16 + g];
        rowlab[2 * i + 1] = sla[wm * 32 + i * 16 + g + 8];
    }
    int collab[16];
    #pragma unroll
    for (int j = 0; j < 8; j++) {
        collab[2 * j + 0] = slb[wn * 64 + j * 8 + t4 * 2 + 0];
        collab[2 * j + 1] = slb[wn * 64 + j * 8 + t4 * 2 + 1];
    }

    float prow[4], nrow[4];
    #pragma unroll
    for (int k = 0; k < 4; k++) { prow[k] = 0.0f; nrow[k] = 0.0f; }

    #pragma unroll
    for (int i = 0; i < 2; i++)
        #pragma unroll
        for (int j = 0; j < 8; j++)
            #pragma unroll
            for (int v = 0; v < 4; v++) {
                float e = __expf(acc[i][j][v] * kTempInv);
                int h = v >> 1;
                nrow[2 * i + h] += e;
                if (collab[2 * j + (v & 1)] == rowlab[2 * i + h])
                    prow[2 * i + h] += e;
            }

    // reduce across the 4 lanes of each quad (same row, different cols)
    #pragma unroll
    for (int off = 1; off <= 2; off <<= 1)
        #pragma unroll
        for (int k = 0; k < 4; k++) {
            prow[k] += __shfl_xor_sync(0xffffffffu, prow[k], off);
            nrow[k] += __shfl_xor_sync(0xffffffffu, nrow[k], off);
        }

    if (t4 == 0) {
        #pragma unroll
        for (int k = 0; k < 4; k++) {
            int row = wm * 32 + (k >> 1) * 16 + g + (k & 1) * 8;
            atomicAdd(&spos[row], prow[k]);
            atomicAdd(&sneg[row], nrow[k]);
        }
    }
    __syncthreads();
    if (tid < BM) {
        atomicAdd(&g_pos[bm0 + tid], (double)spos[tid]);
        atomicAdd(&g_neg[bm0 + tid], (double)sneg[tid]);
    }
}

// ---------------------------------------------------------------------------
// finalize stage 1: 16 blocks x 512 threads, partial sums -> atomic double
// ---------------------------------------------------------------------------
__global__ void finalize1_kernel() {
    int t = blockIdx.x * blockDim.x + threadIdx.x;  // 8192 threads total
    double p = g_pos[t];
    if (p < 1e-8) p = 1e-8;
    double local = (double)logf((float)(p / g_neg[t]));
    #pragma unroll
    for (int off = 16; off > 0; off >>= 1)
        local += __shfl_xor_sync(0xffffffffu, local, off);
    __shared__ double ws[16];
    int lt = threadIdx.x;
    if ((lt & 31) == 0) ws[lt >> 5] = local;
    __syncthreads();
    if (lt < 16) {
        double x = ws[lt];
        #pragma unroll
        for (int off = 8; off > 0; off >>= 1)
            x += __shfl_xor_sync(0xffffffffu, x, off);
        if (lt == 0) atomicAdd(&g_loss, x);
    }
}

__global__ void finalize2_kernel(float* __restrict__ out) {
    out[0] = (float)(-g_loss / (double)NROWS);
}

// ---------------------------------------------------------------------------
extern "C" void kernel_launch(void* const* d_in, const int* in_sizes, int n_in,
                              void* d_out, int out_size) {
    const float* fa = (const float*)d_in[0];
    const float* fb = (const float*)d_in[1];
    const int*   la = (const int*)d_in[2];
    const int*   lb = (const int*)d_in[3];
    float* out = (float*)d_out;

    cudaFuncSetAttribute(gemm_mma_kernel,
                         cudaFuncAttributeMaxDynamicSharedMemorySize, SMEM_TOTAL);

    normalize_kernel<<<2 * NROWS, 256>>>(fa, fb);
    dim3 grid(NROWS / BN, NROWS / BM);
    gemm_mma_kernel<<<grid, THREADS, SMEM_TOTAL>>>(la, lb);
    finalize1_kernel<<<16, 512>>>();
    finalize2_kernel<<<1, 1>>>(out);
}